// round 13
// baseline (speedup 1.0000x reference)
#include <cuda_runtime.h>
#include <cuda_fp16.h>
#include <math.h>
#include <stdint.h>

// ===========================================================================
// B=8192, S=2, E=1024 -> 16384 token rows. All GEMMs NT vs (out,in) weights.
// GEMM: plain fp16 mma.sync m16n8k16, fp32 accumulate.
// R13 (= R12 resubmit; container infra failure last round):
// CTA 256x128, warp tile 64x64 (4Mx2N), K-chunk 64, 3-stage cp.async
// (48KB stages, 144KB), 1 barrier/chunk, early issue c+2. LDS:HMMA balanced.
// qkv intermediate fp16. Merged launches: QKV N=3072; FFN pairs via .z.
// ===========================================================================

#define NTOK 16384ull

__device__ __align__(256) __half g_qkv[NTOK * 3072];
__device__ __align__(256) float g_out1[NTOK * 1024];
__device__ __align__(256) __half g_xs[NTOK * 1024];
__device__ __align__(256) __half g_cc[NTOK * 1024];
__device__ __align__(256) __half g_os[NTOK * 1024];
__device__ __align__(256) __half g_h[2ull * 8192 * 2048];
__device__ __align__(256) __half g_w[12ull * 1024 * 1024];

// ---------------- helpers ---------------------------------------------------
__device__ __forceinline__ uint32_t smem_u32(const void* p) {
    return (uint32_t)__cvta_generic_to_shared(p);
}
__device__ __forceinline__ void cp16(uint32_t dst, const void* src) {
    asm volatile("cp.async.cg.shared.global [%0], [%1], 16;\n" :: "r"(dst), "l"(src));
}
__device__ __forceinline__ void cp_commit() {
    asm volatile("cp.async.commit_group;\n" ::: "memory");
}
__device__ __forceinline__ void cp_wait1() {
    asm volatile("cp.async.wait_group 1;\n" ::: "memory");
}
__device__ __forceinline__ void ldsm4(uint32_t (&r)[4], uint32_t addr) {
    asm volatile("ldmatrix.sync.aligned.m8n8.x4.shared.b16 {%0,%1,%2,%3}, [%4];"
                 : "=r"(r[0]), "=r"(r[1]), "=r"(r[2]), "=r"(r[3]) : "r"(addr));
}
__device__ __forceinline__ void mma_f16(float (&d)[4], const uint32_t (&a)[4],
                                        uint32_t b0, uint32_t b1) {
    asm volatile(
        "mma.sync.aligned.m16n8k16.row.col.f32.f16.f16.f32 "
        "{%0,%1,%2,%3}, {%4,%5,%6,%7}, {%8,%9}, {%0,%1,%2,%3};"
        : "+f"(d[0]), "+f"(d[1]), "+f"(d[2]), "+f"(d[3])
        : "r"(a[0]), "r"(a[1]), "r"(a[2]), "r"(a[3]), "r"(b0), "r"(b1));
}

// ---------------------------------------------------------------------------
// Weight convert (all 8 weights in one launch): fp32 -> fp16
// ---------------------------------------------------------------------------
struct WPtrs { const float* w[8]; };

__global__ void __launch_bounds__(256) wconv8(WPtrs wp, __half* __restrict__ hi) {
    const size_t M1 = 1024ull * 1024;
    int bid = blockIdx.x;
    int seg, lb;
    size_t dstoff;
    if (bid < 4096) {
        seg = bid >> 10;
        lb = bid & 1023;
        dstoff = (size_t)seg * M1;
    } else {
        seg = 4 + ((bid - 4096) >> 11);
        lb = (bid - 4096) & 2047;
        dstoff = (size_t)(4 + 2 * (seg - 4)) * M1;
    }
    size_t i = ((size_t)lb * 256 + threadIdx.x) * 4;
    float4 v = *(const float4*)(wp.w[seg] + i);
    *(__half2*)(hi + dstoff + i)     = __floats2half2_rn(v.x, v.y);
    *(__half2*)(hi + dstoff + i + 2) = __floats2half2_rn(v.z, v.w);
}

// ---------------------------------------------------------------------------
// Joint LayerNorm over 2048 elems per batch -> fp16
// ---------------------------------------------------------------------------
__global__ void __launch_bounds__(256) ln_kernel(const float* __restrict__ x,
                                                 const float* __restrict__ w,
                                                 const float* __restrict__ bb,
                                                 __half* __restrict__ y) {
    int batch = blockIdx.x;
    int tid = threadIdx.x;
    const float4* xv = (const float4*)(x + (size_t)batch * 2048);
    float4 v0 = xv[tid];
    float4 v1 = xv[tid + 256];
    float s  = v0.x + v0.y + v0.z + v0.w + v1.x + v1.y + v1.z + v1.w;
    float ss = v0.x*v0.x + v0.y*v0.y + v0.z*v0.z + v0.w*v0.w
             + v1.x*v1.x + v1.y*v1.y + v1.z*v1.z + v1.w*v1.w;
#pragma unroll
    for (int o = 16; o > 0; o >>= 1) {
        s  += __shfl_xor_sync(0xffffffffu, s,  o);
        ss += __shfl_xor_sync(0xffffffffu, ss, o);
    }
    __shared__ float rs[8], rss[8];
    __shared__ float s_mean, s_rstd;
    if ((tid & 31) == 0) { rs[tid >> 5] = s; rss[tid >> 5] = ss; }
    __syncthreads();
    if (tid == 0) {
        float ts = 0.f, tss = 0.f;
#pragma unroll
        for (int i = 0; i < 8; i++) { ts += rs[i]; tss += rss[i]; }
        float m   = ts * (1.f / 2048.f);
        float var = tss * (1.f / 2048.f) - m * m;
        s_mean = m;
        s_rstd = rsqrtf(var + 1e-5f);
    }
    __syncthreads();
    float m = s_mean, r = s_rstd;
    const float4* wv = (const float4*)w;
    const float4* bv = (const float4*)bb;
    float4 w0 = wv[tid], w1 = wv[tid + 256];
    float4 b0 = bv[tid], b1 = bv[tid + 256];
    size_t base = (size_t)batch * 2048 + tid * 4;
    *(__half2*)(y + base) = __floats2half2_rn(
        (v0.x - m) * r * w0.x + b0.x, (v0.y - m) * r * w0.y + b0.y);
    *(__half2*)(y + base + 2) = __floats2half2_rn(
        (v0.z - m) * r * w0.z + b0.z, (v0.w - m) * r * w0.w + b0.w);
    *(__half2*)(y + base + 1024) = __floats2half2_rn(
        (v1.x - m) * r * w1.x + b1.x, (v1.y - m) * r * w1.y + b1.y);
    *(__half2*)(y + base + 1026) = __floats2half2_rn(
        (v1.z - m) * r * w1.z + b1.z, (v1.w - m) * r * w1.w + b1.w);
}

// ---------------------------------------------------------------------------
// Attention per batch (S=2; head h = col % 16), fp16 qkv -> concat fp16
// qkv layout: row (b*2+s) of 3072 halves = [q(1024) | k(1024) | v(1024)]
// ---------------------------------------------------------------------------
__global__ void __launch_bounds__(128) attn_kernel(const __half* __restrict__ qkv,
                                                   __half* __restrict__ oc) {
    int b = blockIdx.x;
    int tid = threadIdx.x;
    __shared__ float sq[2048], sk[2048], sv[2048];
    __shared__ float ssc[16][2][2];
    __shared__ float sp[16][2][2];

#pragma unroll
    for (int s = 0; s < 2; s++) {
        const __half2* row = (const __half2*)(qkv + ((size_t)b * 2 + s) * 3072);
#pragma unroll
        for (int i = tid; i < 512; i += 128) {
            ((float2*)sq)[s * 512 + i] = __half22float2(row[i]);
            ((float2*)sk)[s * 512 + i] = __half22float2(row[512 + i]);
            ((float2*)sv)[s * 512 + i] = __half22float2(row[1024 + i]);
        }
    }
    __syncthreads();

    if (tid < 64) {
        int h = tid >> 2, s = (tid >> 1) & 1, t = tid & 1;
        float acc = 0.f;
#pragma unroll 8
        for (int d = 0; d < 64; d++)
            acc += sq[s * 1024 + d * 16 + h] * sk[t * 1024 + d * 16 + h];
        ssc[h][s][t] = acc * 0.125f;
    }
    __syncthreads();

    if (tid < 32) {
        int h = tid >> 1, s = tid & 1;
        float a0 = ssc[h][s][0], a1 = ssc[h][s][1];
        float mx = fmaxf(a0, a1);
        float e0 = expf(a0 - mx), e1 = expf(a1 - mx);
        float inv = 1.f / (e0 + e1);
        sp[h][s][0] = e0 * inv;
        sp[h][s][1] = e1 * inv;
    }
    __syncthreads();

    size_t ob = (size_t)b * 2048;
#pragma unroll
    for (int i = tid * 2; i < 2048; i += 256) {
        int s = i >> 10;
        int c0 = i & 1023;
        int h0 = c0 & 15, h1 = (c0 + 1) & 15;
        float va = sp[h0][s][0] * sv[c0] + sp[h0][s][1] * sv[1024 + c0];
        float vb = sp[h1][s][0] * sv[c0 + 1] + sp[h1][s][1] * sv[1024 + c0 + 1];
        *(__half2*)(oc + ob + i) = __floats2half2_rn(va, vb);
    }
}

// ---------------------------------------------------------------------------
// Plain fp16 mma.sync GEMM:  C = epi( A @ B^T ).
// CTA 256x128, K-chunk 64, 8 warps (4M x 2N, warp tile 64x64), 3-stage
// cp.async (A 32KB + B 16KB = 48KB stages, 144KB), one barrier per chunk,
// early issue for c+2. smem rows 128B; swizzle c16 ^ (row & 7).
// gridDim.z indexes pointer sets (merged launches).
// EPI: 0 plain -> fp16; 1 +res -> fp32; 2 tanh(+bias)->fp16; 3 tanh(+bias)+res
// ---------------------------------------------------------------------------
#define A_OFF 0
#define B_OFF 32768
#define STAGE_BYTES 49152
#define NSTAGE 3
#define GEMM_SMEM (NSTAGE * STAGE_BYTES)

struct GPair {
    const __half *A[2], *B[2];
    const float *bias[2], *res[2];
    float *C[2];
    __half *Ch[2];
};

template <int EPI>
__global__ void __launch_bounds__(256) gemm_mma(
    GPair P, int lda, int ldb, int ldres, int ldc, int K)
{
    extern __shared__ __align__(128) char smem[];
    const uint32_t sb = smem_u32(smem);
    const int z = blockIdx.z;
    const int tid = threadIdx.x;
    const int wid = tid >> 5, lane = tid & 31;
    const int bm = blockIdx.y * 256, bn = blockIdx.x * 128;
    const int wm = wid & 3, wn = wid >> 2;   // 4M x 2N, warp tile 64x64
    const int nch = K >> 6;

    float acc[4][8][4];
#pragma unroll
    for (int i = 0; i < 4; i++)
#pragma unroll
        for (int j = 0; j < 8; j++)
#pragma unroll
            for (int r = 0; r < 4; r++) acc[i][j][r] = 0.f;

    // ---- load geometry ------------------------------------------------------
    // lrow = tid>>3 (0..31), lc16 = tid&7. Row step 32 keeps swizzle bits.
    // A: 256 rows -> 8 passes; B: 128 rows -> 4 passes.
    const int lrow = tid >> 3, lc16 = tid & 7;
    const uint32_t s_off = (uint32_t)(lrow * 128 + ((lc16 ^ (lrow & 7)) << 4));
    const uint32_t a_g0 = (uint32_t)(((bm + lrow) * lda + lc16 * 8) * 2);
    const uint32_t b_g0 = (uint32_t)(((bn + lrow) * ldb + lc16 * 8) * 2);
    const uint32_t a_gstep = (uint32_t)(lda << 6);   // 32 rows * lda * 2B
    const uint32_t b_gstep = (uint32_t)(ldb << 6);
    const char* Ap = (const char*)P.A[z];
    const char* Bp = (const char*)P.B[z];

    auto load_stage = [&](int stage, int c) {
        if (c < nch) {
            const uint32_t s0 = sb + stage * STAGE_BYTES;
            const uint32_t kadd = (uint32_t)c << 7;   // c*128 bytes
#pragma unroll
            for (int j = 0; j < 8; j++)
                cp16(s0 + A_OFF + s_off + j * 4096, Ap + a_g0 + j * a_gstep + kadd);
#pragma unroll
            for (int j = 0; j < 4; j++)
                cp16(s0 + B_OFF + s_off + j * 4096, Bp + b_g0 + j * b_gstep + kadd);
        }
        cp_commit();
    };

    // ---- ldmatrix per-lane geometry ----------------------------------------
    const int r16 = (lane & 7) + (((lane >> 3) & 1) << 3);
    const int cko = lane >> 4;
    uint32_t arow[4]; int axr[4];
#pragma unroll
    for (int tm = 0; tm < 4; tm++) {
        int row = wm * 64 + tm * 16 + r16;
        arow[tm] = row * 128;
        axr[tm] = row & 7;
    }
    uint32_t brow[4]; int bxr[4];
#pragma unroll
    for (int g = 0; g < 4; g++) {
        int row = wn * 64 + g * 16 + r16;
        brow[g] = row * 128;
        bxr[g] = row & 7;
    }

    load_stage(0, 0);
    load_stage(1, 1);

    int stage = 0;
    for (int c = 0; c < nch; c++) {
        cp_wait1();           // chunk c resident
        __syncthreads();      // all warps done with chunk c-1's stage
        int nstage = stage + 2;
        if (nstage >= NSTAGE) nstage -= NSTAGE;
        load_stage(nstage, c + 2);   // overwrites c-1's stage (safe)

        const uint32_t s0 = sb + stage * STAGE_BYTES;
#pragma unroll
        for (int kk = 0; kk < 4; kk++) {
            const int j16 = (kk << 1) | cko;
            uint32_t ar[4][4], br[4][4];
#pragma unroll
            for (int tm = 0; tm < 4; tm++) {
                uint32_t off = arow[tm] + ((j16 ^ axr[tm]) << 4);
                ldsm4(ar[tm], s0 + A_OFF + off);
            }
#pragma unroll
            for (int g = 0; g < 4; g++) {
                uint32_t off = brow[g] + ((j16 ^ bxr[g]) << 4);
                ldsm4(br[g], s0 + B_OFF + off);
            }
#pragma unroll
            for (int tm = 0; tm < 4; tm++)
#pragma unroll
                for (int tn = 0; tn < 8; tn++) {
                    const int g = tn >> 1, h = tn & 1;
                    mma_f16(acc[tm][tn], ar[tm], br[g][h], br[g][h + 2]);
                }
        }
        if (++stage >= NSTAGE) stage -= NSTAGE;
    }

    // Epilogue
    const float* bias = P.bias[z];
    const float* res  = P.res[z];
    float* C = P.C[z];
    __half* Ch = P.Ch[z];
#pragma unroll
    for (int tm = 0; tm < 4; tm++) {
#pragma unroll
        for (int tn = 0; tn < 8; tn++) {
            const int row0 = bm + wm * 64 + tm * 16 + (lane >> 2);
            const int col  = bn + wn * 64 + tn * 8 + (lane & 3) * 2;
#pragma unroll
            for (int hrow = 0; hrow < 2; hrow++) {
                const int row = row0 + hrow * 8;
                float d0 = acc[tm][tn][hrow * 2];
                float d1 = acc[tm][tn][hrow * 2 + 1];
                if (EPI == 0) {
                    *(__half2*)(Ch + (size_t)row * ldc + col) =
                        __floats2half2_rn(d0, d1);
                } else if (EPI == 1) {
                    float2 rv = *(const float2*)(res + (size_t)row * ldres + col);
                    *(float2*)(C + (size_t)row * ldc + col) =
                        make_float2(d0 + rv.x, d1 + rv.y);
                } else if (EPI == 2) {
                    float2 bv = *(const float2*)(bias + col);
                    *(__half2*)(Ch + (size_t)row * ldc + col) =
                        __floats2half2_rn(tanhf(d0 + bv.x), tanhf(d1 + bv.y));
                } else {
                    float2 bv = *(const float2*)(bias + col);
                    float2 rv = *(const float2*)(res + (size_t)row * ldres + col);
                    *(float2*)(C + (size_t)row * ldc + col) =
                        make_float2(tanhf(d0 + bv.x) + rv.x, tanhf(d1 + bv.y) + rv.y);
                }
            }
        }
    }
}

// ---------------------------------------------------------------------------
// Orchestration
// ---------------------------------------------------------------------------
extern "C" void kernel_launch(void* const* d_in, const int* in_sizes, int n_in,
                              void* d_out, int out_size) {
    (void)in_sizes; (void)n_in; (void)out_size;
    const float* input = (const float*)d_in[0];
    const float* ln1w = (const float*)d_in[5];
    const float* ln1b = (const float*)d_in[6];
    const float* ln2w = (const float*)d_in[7];
    const float* ln2b = (const float*)d_in[8];
    const float* f1b1 = (const float*)d_in[10];
    const float* f1b2 = (const float*)d_in[12];
    const float* f2b1 = (const float*)d_in[14];
    const float* f2b2 = (const float*)d_in[16];
    float* out = (float*)d_out;

    float* out1;
    __half *qkv, *xs, *cc, *os, *h, *w;
    cudaGetSymbolAddress((void**)&qkv, g_qkv);
    cudaGetSymbolAddress((void**)&out1, g_out1);
    cudaGetSymbolAddress((void**)&xs, g_xs);
    cudaGetSymbolAddress((void**)&cc, g_cc);
    cudaGetSymbolAddress((void**)&os, g_os);
    cudaGetSymbolAddress((void**)&h, g_h);
    cudaGetSymbolAddress((void**)&w, g_w);

    const size_t M1 = 1024ull * 1024;
    __half *wqkv = w;                    // rows 0..3071 (Wq|Wk|Wv)
    __half *wo   = w + 3*M1;
    __half *f1w1 = w + 4*M1;
    __half *f2w1 = w + 6*M1;
    __half *f1w2 = w + 8*M1;
    __half *f2w2 = w + 10*M1;
    __half *h0 = h, *h1 = h + 8192ull * 2048;

    cudaFuncSetAttribute(gemm_mma<0>, cudaFuncAttributeMaxDynamicSharedMemorySize, GEMM_SMEM);
    cudaFuncSetAttribute(gemm_mma<1>, cudaFuncAttributeMaxDynamicSharedMemorySize, GEMM_SMEM);
    cudaFuncSetAttribute(gemm_mma<2>, cudaFuncAttributeMaxDynamicSharedMemorySize, GEMM_SMEM);
    cudaFuncSetAttribute(gemm_mma<3>, cudaFuncAttributeMaxDynamicSharedMemorySize, GEMM_SMEM);

    // weight converts
    WPtrs wp;
    wp.w[0] = (const float*)d_in[1];   // Wq
    wp.w[1] = (const float*)d_in[2];   // Wk
    wp.w[2] = (const float*)d_in[3];   // Wv
    wp.w[3] = (const float*)d_in[4];   // Wo
    wp.w[4] = (const float*)d_in[9];   // f1w1
    wp.w[5] = (const float*)d_in[13];  // f2w1
    wp.w[6] = (const float*)d_in[11];  // f1w2
    wp.w[7] = (const float*)d_in[15];  // f2w2
    wconv8<<<12288, 256>>>(wp, w);

    // LN1 -> xs (fp16)
    ln_kernel<<<8192, 256>>>(input, ln1w, ln1b, xs);

    // QKV merged projection (M=16384, N=3072, K=1024) -> qkv (fp16)
    {
        GPair P{};
        P.A[0] = P.A[1] = xs;
        P.B[0] = P.B[1] = wqkv;
        P.Ch[0] = P.Ch[1] = qkv;
        gemm_mma<0><<<dim3(24, 64, 1), 256, GEMM_SMEM>>>(P, 1024, 1024, 0, 3072, 1024);
    }

    // attention -> concat (fp16)
    attn_kernel<<<8192, 128>>>(qkv, cc);

    // O projection + residual -> out1 (fp32)
    {
        GPair P{};
        P.A[0] = P.A[1] = cc;
        P.B[0] = P.B[1] = wo;
        P.res[0] = P.res[1] = input;
        P.C[0] = P.C[1] = out1;
        gemm_mma<1><<<dim3(8, 64, 1), 256, GEMM_SMEM>>>(P, 1024, 1024, 1024, 1024, 1024);
    }

    // LN2 -> os (fp16)
    ln_kernel<<<8192, 256>>>(out1, ln2w, ln2b, os);

    // FFN layer 1, both slots in one launch (M=8192, N=2048, K=1024) -> h fp16
    {
        GPair P{};
        P.A[0] = os;   P.A[1] = os + 1024;
        P.B[0] = f1w1; P.B[1] = f2w1;
        P.bias[0] = f1b1; P.bias[1] = f2b1;
        P.Ch[0] = h0; P.Ch[1] = h1;
        gemm_mma<2><<<dim3(16, 32, 2), 256, GEMM_SMEM>>>(P, 2048, 1024, 0, 2048, 1024);
    }

    // FFN layer 2 + residual, both slots in one launch (M=8192, N=1024, K=2048)
    {
        GPair P{};
        P.A[0] = h0;   P.A[1] = h1;
        P.B[0] = f1w2; P.B[1] = f2w2;
        P.bias[0] = f1b2; P.bias[1] = f2b2;
        P.res[0] = out1;  P.res[1] = out1 + 1024;
        P.C[0] = out;     P.C[1] = out + 1024;
        gemm_mma<3><<<dim3(8, 32, 2), 256, GEMM_SMEM>>>(P, 2048, 2048, 2048, 2048, 2048);
    }
}

// round 14
// speedup vs baseline: 1.0153x; 1.0153x over previous
#include <cuda_runtime.h>
#include <cuda_fp16.h>
#include <math.h>
#include <stdint.h>

// ===========================================================================
// B=8192, S=2, E=1024 -> 16384 token rows. All GEMMs NT vs (out,in) weights.
// GEMM: plain fp16 mma.sync m16n8k16, fp32 accumulate (R11 config verbatim:
// 128x128 tile, K-chunk 128, 3-stage 64KB cp.async, 8 warps 2Mx4N).
// R14 additions: fp16 qkv + fp16 attention (R13-proven), wconv+LN1 fused
// into one grid-partitioned prep kernel. Merged launches: QKV N=3072,
// FFN pairs via gridDim.z.
// ===========================================================================

#define NTOK 16384ull

__device__ __align__(256) __half g_qkv[NTOK * 3072];
__device__ __align__(256) float g_out1[NTOK * 1024];
__device__ __align__(256) __half g_xs[NTOK * 1024];
__device__ __align__(256) __half g_cc[NTOK * 1024];
__device__ __align__(256) __half g_os[NTOK * 1024];
__device__ __align__(256) __half g_h[2ull * 8192 * 2048];
__device__ __align__(256) __half g_w[12ull * 1024 * 1024];

// ---------------- helpers ---------------------------------------------------
__device__ __forceinline__ uint32_t smem_u32(const void* p) {
    return (uint32_t)__cvta_generic_to_shared(p);
}
__device__ __forceinline__ void cp16(uint32_t dst, const void* src) {
    asm volatile("cp.async.cg.shared.global [%0], [%1], 16;\n" :: "r"(dst), "l"(src));
}
__device__ __forceinline__ void cp_commit() {
    asm volatile("cp.async.commit_group;\n" ::: "memory");
}
__device__ __forceinline__ void cp_wait1() {
    asm volatile("cp.async.wait_group 1;\n" ::: "memory");
}
__device__ __forceinline__ void ldsm4(uint32_t (&r)[4], uint32_t addr) {
    asm volatile("ldmatrix.sync.aligned.m8n8.x4.shared.b16 {%0,%1,%2,%3}, [%4];"
                 : "=r"(r[0]), "=r"(r[1]), "=r"(r[2]), "=r"(r[3]) : "r"(addr));
}
__device__ __forceinline__ void mma_f16(float (&d)[4], const uint32_t (&a)[4],
                                        uint32_t b0, uint32_t b1) {
    asm volatile(
        "mma.sync.aligned.m16n8k16.row.col.f32.f16.f16.f32 "
        "{%0,%1,%2,%3}, {%4,%5,%6,%7}, {%8,%9}, {%0,%1,%2,%3};"
        : "+f"(d[0]), "+f"(d[1]), "+f"(d[2]), "+f"(d[3])
        : "r"(a[0]), "r"(a[1]), "r"(a[2]), "r"(a[3]), "r"(b0), "r"(b1));
}

// ---------------------------------------------------------------------------
// Fused prep: blocks [0,12288) convert the 8 weights fp32->fp16;
// blocks [12288,20480) do joint LayerNorm-1 (2048 elems/batch) -> fp16.
// Disjoint inputs/outputs; both memory-bound; overlap saturates DRAM.
// ---------------------------------------------------------------------------
struct WPtrs { const float* w[8]; };

__global__ void __launch_bounds__(256) prep_kernel(
    WPtrs wp, __half* __restrict__ wout,
    const float* __restrict__ x, const float* __restrict__ lw,
    const float* __restrict__ lb, __half* __restrict__ y)
{
    int bid = blockIdx.x;
    int tid = threadIdx.x;
    if (bid < 12288) {
        const size_t M1 = 1024ull * 1024;
        int seg, lbk;
        size_t dstoff;
        if (bid < 4096) {
            seg = bid >> 10;
            lbk = bid & 1023;
            dstoff = (size_t)seg * M1;
        } else {
            seg = 4 + ((bid - 4096) >> 11);
            lbk = (bid - 4096) & 2047;
            dstoff = (size_t)(4 + 2 * (seg - 4)) * M1;
        }
        size_t i = ((size_t)lbk * 256 + tid) * 4;
        float4 v = *(const float4*)(wp.w[seg] + i);
        *(__half2*)(wout + dstoff + i)     = __floats2half2_rn(v.x, v.y);
        *(__half2*)(wout + dstoff + i + 2) = __floats2half2_rn(v.z, v.w);
        return;
    }

    // ---- LayerNorm path ----
    int batch = bid - 12288;
    const float4* xv = (const float4*)(x + (size_t)batch * 2048);
    float4 v0 = xv[tid];
    float4 v1 = xv[tid + 256];
    float s  = v0.x + v0.y + v0.z + v0.w + v1.x + v1.y + v1.z + v1.w;
    float ss = v0.x*v0.x + v0.y*v0.y + v0.z*v0.z + v0.w*v0.w
             + v1.x*v1.x + v1.y*v1.y + v1.z*v1.z + v1.w*v1.w;
#pragma unroll
    for (int o = 16; o > 0; o >>= 1) {
        s  += __shfl_xor_sync(0xffffffffu, s,  o);
        ss += __shfl_xor_sync(0xffffffffu, ss, o);
    }
    __shared__ float rs[8], rss[8];
    __shared__ float s_mean, s_rstd;
    if ((tid & 31) == 0) { rs[tid >> 5] = s; rss[tid >> 5] = ss; }
    __syncthreads();
    if (tid == 0) {
        float ts = 0.f, tss = 0.f;
#pragma unroll
        for (int i = 0; i < 8; i++) { ts += rs[i]; tss += rss[i]; }
        float m   = ts * (1.f / 2048.f);
        float var = tss * (1.f / 2048.f) - m * m;
        s_mean = m;
        s_rstd = rsqrtf(var + 1e-5f);
    }
    __syncthreads();
    float m = s_mean, r = s_rstd;
    const float4* wv = (const float4*)lw;
    const float4* bv = (const float4*)lb;
    float4 w0 = wv[tid], w1 = wv[tid + 256];
    float4 b0 = bv[tid], b1 = bv[tid + 256];
    size_t base = (size_t)batch * 2048 + tid * 4;
    *(__half2*)(y + base) = __floats2half2_rn(
        (v0.x - m) * r * w0.x + b0.x, (v0.y - m) * r * w0.y + b0.y);
    *(__half2*)(y + base + 2) = __floats2half2_rn(
        (v0.z - m) * r * w0.z + b0.z, (v0.w - m) * r * w0.w + b0.w);
    *(__half2*)(y + base + 1024) = __floats2half2_rn(
        (v1.x - m) * r * w1.x + b1.x, (v1.y - m) * r * w1.y + b1.y);
    *(__half2*)(y + base + 1026) = __floats2half2_rn(
        (v1.z - m) * r * w1.z + b1.z, (v1.w - m) * r * w1.w + b1.w);
}

// ---------------------------------------------------------------------------
// Standalone joint LayerNorm (for LN2, fp32 in -> fp16 out)
// ---------------------------------------------------------------------------
__global__ void __launch_bounds__(256) ln_kernel(const float* __restrict__ x,
                                                 const float* __restrict__ w,
                                                 const float* __restrict__ bb,
                                                 __half* __restrict__ y) {
    int batch = blockIdx.x;
    int tid = threadIdx.x;
    const float4* xv = (const float4*)(x + (size_t)batch * 2048);
    float4 v0 = xv[tid];
    float4 v1 = xv[tid + 256];
    float s  = v0.x + v0.y + v0.z + v0.w + v1.x + v1.y + v1.z + v1.w;
    float ss = v0.x*v0.x + v0.y*v0.y + v0.z*v0.z + v0.w*v0.w
             + v1.x*v1.x + v1.y*v1.y + v1.z*v1.z + v1.w*v1.w;
#pragma unroll
    for (int o = 16; o > 0; o >>= 1) {
        s  += __shfl_xor_sync(0xffffffffu, s,  o);
        ss += __shfl_xor_sync(0xffffffffu, ss, o);
    }
    __shared__ float rs[8], rss[8];
    __shared__ float s_mean, s_rstd;
    if ((tid & 31) == 0) { rs[tid >> 5] = s; rss[tid >> 5] = ss; }
    __syncthreads();
    if (tid == 0) {
        float ts = 0.f, tss = 0.f;
#pragma unroll
        for (int i = 0; i < 8; i++) { ts += rs[i]; tss += rss[i]; }
        float m   = ts * (1.f / 2048.f);
        float var = tss * (1.f / 2048.f) - m * m;
        s_mean = m;
        s_rstd = rsqrtf(var + 1e-5f);
    }
    __syncthreads();
    float m = s_mean, r = s_rstd;
    const float4* wv = (const float4*)w;
    const float4* bv = (const float4*)bb;
    float4 w0 = wv[tid], w1 = wv[tid + 256];
    float4 b0 = bv[tid], b1 = bv[tid + 256];
    size_t base = (size_t)batch * 2048 + tid * 4;
    *(__half2*)(y + base) = __floats2half2_rn(
        (v0.x - m) * r * w0.x + b0.x, (v0.y - m) * r * w0.y + b0.y);
    *(__half2*)(y + base + 2) = __floats2half2_rn(
        (v0.z - m) * r * w0.z + b0.z, (v0.w - m) * r * w0.w + b0.w);
    *(__half2*)(y + base + 1024) = __floats2half2_rn(
        (v1.x - m) * r * w1.x + b1.x, (v1.y - m) * r * w1.y + b1.y);
    *(__half2*)(y + base + 1026) = __floats2half2_rn(
        (v1.z - m) * r * w1.z + b1.z, (v1.w - m) * r * w1.w + b1.w);
}

// ---------------------------------------------------------------------------
// Attention per batch (S=2; head h = col % 16), fp16 qkv -> concat fp16
// qkv layout: row (b*2+s) of 3072 halves = [q(1024) | k(1024) | v(1024)]
// ---------------------------------------------------------------------------
__global__ void __launch_bounds__(128) attn_kernel(const __half* __restrict__ qkv,
                                                   __half* __restrict__ oc) {
    int b = blockIdx.x;
    int tid = threadIdx.x;
    __shared__ float sq[2048], sk[2048], sv[2048];
    __shared__ float ssc[16][2][2];
    __shared__ float sp[16][2][2];

#pragma unroll
    for (int s = 0; s < 2; s++) {
        const __half2* row = (const __half2*)(qkv + ((size_t)b * 2 + s) * 3072);
#pragma unroll
        for (int i = tid; i < 512; i += 128) {
            ((float2*)sq)[s * 512 + i] = __half22float2(row[i]);
            ((float2*)sk)[s * 512 + i] = __half22float2(row[512 + i]);
            ((float2*)sv)[s * 512 + i] = __half22float2(row[1024 + i]);
        }
    }
    __syncthreads();

    if (tid < 64) {
        int h = tid >> 2, s = (tid >> 1) & 1, t = tid & 1;
        float acc = 0.f;
#pragma unroll 8
        for (int d = 0; d < 64; d++)
            acc += sq[s * 1024 + d * 16 + h] * sk[t * 1024 + d * 16 + h];
        ssc[h][s][t] = acc * 0.125f;
    }
    __syncthreads();

    if (tid < 32) {
        int h = tid >> 1, s = tid & 1;
        float a0 = ssc[h][s][0], a1 = ssc[h][s][1];
        float mx = fmaxf(a0, a1);
        float e0 = expf(a0 - mx), e1 = expf(a1 - mx);
        float inv = 1.f / (e0 + e1);
        sp[h][s][0] = e0 * inv;
        sp[h][s][1] = e1 * inv;
    }
    __syncthreads();

    size_t ob = (size_t)b * 2048;
#pragma unroll
    for (int i = tid * 2; i < 2048; i += 256) {
        int s = i >> 10;
        int c0 = i & 1023;
        int h0 = c0 & 15, h1 = (c0 + 1) & 15;
        float va = sp[h0][s][0] * sv[c0] + sp[h0][s][1] * sv[1024 + c0];
        float vb = sp[h1][s][0] * sv[c0 + 1] + sp[h1][s][1] * sv[1024 + c0 + 1];
        *(__half2*)(oc + ob + i) = __floats2half2_rn(va, vb);
    }
}

// ---------------------------------------------------------------------------
// Plain fp16 mma.sync GEMM (R11 config):  C = epi( A @ B^T ).
// Tile 128x128, K-chunk 128, 8 warps (2M x 4N), 3-stage cp.async (64KB
// stages, 192KB), one barrier per chunk, early issue for c+2.
// smem rows 256B (128 fp16); swizzle: c16 ^ (row & 7).
// gridDim.z indexes pointer sets (merged launches).
// EPI: 0 plain -> fp16; 1 +res -> fp32; 2 tanh(+bias)->fp16; 3 tanh(+bias)+res
// ---------------------------------------------------------------------------
#define A_OFF 0
#define B_OFF 32768
#define STAGE_BYTES 65536
#define NSTAGE 3
#define GEMM_SMEM (NSTAGE * STAGE_BYTES)

struct GPair {
    const __half *A[2], *B[2];
    const float *bias[2], *res[2];
    float *C[2];
    __half *Ch[2];
};

template <int EPI>
__global__ void __launch_bounds__(256) gemm_mma(
    GPair P, int lda, int ldb, int ldres, int ldc, int K)
{
    extern __shared__ __align__(128) char smem[];
    const uint32_t sb = smem_u32(smem);
    const int z = blockIdx.z;
    const int tid = threadIdx.x;
    const int wid = tid >> 5, lane = tid & 31;
    const int bm = blockIdx.y * 128, bn = blockIdx.x * 128;
    const int wm = wid & 1, wn = wid >> 1;
    const int nch = K >> 7;

    float acc[4][4][4];
#pragma unroll
    for (int i = 0; i < 4; i++)
#pragma unroll
        for (int j = 0; j < 4; j++)
#pragma unroll
            for (int r = 0; r < 4; r++) acc[i][j][r] = 0.f;

    // ---- load geometry: 8 passes x 2 matrices, 16B each thread ------------
    const int lrow = tid >> 4, lc16 = tid & 15;
    const uint32_t a_s0 = (uint32_t)(lrow * 256 + ((lc16 ^ (lrow & 7)) << 4));
    const uint32_t a_g0 = (uint32_t)(((bm + lrow) * lda + lc16 * 8) * 2);
    const uint32_t b_g0 = (uint32_t)(((bn + lrow) * ldb + lc16 * 8) * 2);
    const uint32_t a_gstep = (uint32_t)(lda << 5);   // 16 rows * lda * 2B
    const uint32_t b_gstep = (uint32_t)(ldb << 5);
    const char* Ap = (const char*)P.A[z];
    const char* Bp = (const char*)P.B[z];

    auto load_stage = [&](int stage, int c) {
        if (c < nch) {
            const uint32_t s0 = sb + stage * STAGE_BYTES;
            const uint32_t kadd = (uint32_t)c << 8;   // c*256 bytes
#pragma unroll
            for (int j = 0; j < 8; j++) {
                cp16(s0 + A_OFF + a_s0 + j * 4096, Ap + a_g0 + j * a_gstep + kadd);
                cp16(s0 + B_OFF + a_s0 + j * 4096, Bp + b_g0 + j * b_gstep + kadd);
            }
        }
        cp_commit();
    };

    // ---- ldmatrix per-lane geometry ---------------------------------------
    const int r16 = (lane & 7) + (((lane >> 3) & 1) << 3);
    const int cko = lane >> 4;
    uint32_t arow[4]; int axr[4];
#pragma unroll
    for (int tm = 0; tm < 4; tm++) {
        int row = wm * 64 + tm * 16 + r16;
        arow[tm] = row * 256;
        axr[tm] = row & 7;
    }
    uint32_t brow[2]; int bxr[2];
#pragma unroll
    for (int g = 0; g < 2; g++) {
        int row = wn * 32 + g * 16 + r16;
        brow[g] = row * 256;
        bxr[g] = row & 7;
    }

    load_stage(0, 0);
    load_stage(1, 1);

    int stage = 0;
    for (int c = 0; c < nch; c++) {
        cp_wait1();           // chunk c resident
        __syncthreads();      // all warps done with chunk c-1's stage
        int nstage = stage + 2;
        if (nstage >= NSTAGE) nstage -= NSTAGE;
        load_stage(nstage, c + 2);   // overwrites c-1's stage (safe)

        const uint32_t s0 = sb + stage * STAGE_BYTES;
#pragma unroll
        for (int kk = 0; kk < 8; kk++) {
            const int j16 = (kk << 1) | cko;
            uint32_t ar[4][4], br[2][4];
#pragma unroll
            for (int tm = 0; tm < 4; tm++) {
                uint32_t off = arow[tm] + ((j16 ^ axr[tm]) << 4);
                ldsm4(ar[tm], s0 + A_OFF + off);
            }
#pragma unroll
            for (int g = 0; g < 2; g++) {
                uint32_t off = brow[g] + ((j16 ^ bxr[g]) << 4);
                ldsm4(br[g], s0 + B_OFF + off);
            }
#pragma unroll
            for (int tm = 0; tm < 4; tm++)
#pragma unroll
                for (int tn = 0; tn < 4; tn++) {
                    const int g = tn >> 1, h = tn & 1;
                    mma_f16(acc[tm][tn], ar[tm], br[g][h], br[g][h + 2]);
                }
        }
        if (++stage >= NSTAGE) stage -= NSTAGE;
    }

    // Epilogue
    const float* bias = P.bias[z];
    const float* res  = P.res[z];
    float* C = P.C[z];
    __half* Ch = P.Ch[z];
#pragma unroll
    for (int tm = 0; tm < 4; tm++) {
#pragma unroll
        for (int tn = 0; tn < 4; tn++) {
            const int row0 = bm + wm * 64 + tm * 16 + (lane >> 2);
            const int col  = bn + wn * 32 + tn * 8 + (lane & 3) * 2;
#pragma unroll
            for (int hrow = 0; hrow < 2; hrow++) {
                const int row = row0 + hrow * 8;
                float d0 = acc[tm][tn][hrow * 2];
                float d1 = acc[tm][tn][hrow * 2 + 1];
                if (EPI == 0) {
                    *(__half2*)(Ch + (size_t)row * ldc + col) =
                        __floats2half2_rn(d0, d1);
                } else if (EPI == 1) {
                    float2 rv = *(const float2*)(res + (size_t)row * ldres + col);
                    *(float2*)(C + (size_t)row * ldc + col) =
                        make_float2(d0 + rv.x, d1 + rv.y);
                } else if (EPI == 2) {
                    float2 bv = *(const float2*)(bias + col);
                    *(__half2*)(Ch + (size_t)row * ldc + col) =
                        __floats2half2_rn(tanhf(d0 + bv.x), tanhf(d1 + bv.y));
                } else {
                    float2 bv = *(const float2*)(bias + col);
                    float2 rv = *(const float2*)(res + (size_t)row * ldres + col);
                    *(float2*)(C + (size_t)row * ldc + col) =
                        make_float2(tanhf(d0 + bv.x) + rv.x, tanhf(d1 + bv.y) + rv.y);
                }
            }
        }
    }
}

// ---------------------------------------------------------------------------
// Orchestration
// ---------------------------------------------------------------------------
extern "C" void kernel_launch(void* const* d_in, const int* in_sizes, int n_in,
                              void* d_out, int out_size) {
    (void)in_sizes; (void)n_in; (void)out_size;
    const float* input = (const float*)d_in[0];
    const float* ln1w = (const float*)d_in[5];
    const float* ln1b = (const float*)d_in[6];
    const float* ln2w = (const float*)d_in[7];
    const float* ln2b = (const float*)d_in[8];
    const float* f1b1 = (const float*)d_in[10];
    const float* f1b2 = (const float*)d_in[12];
    const float* f2b1 = (const float*)d_in[14];
    const float* f2b2 = (const float*)d_in[16];
    float* out = (float*)d_out;

    float* out1;
    __half *qkv, *xs, *cc, *os, *h, *w;
    cudaGetSymbolAddress((void**)&qkv, g_qkv);
    cudaGetSymbolAddress((void**)&out1, g_out1);
    cudaGetSymbolAddress((void**)&xs, g_xs);
    cudaGetSymbolAddress((void**)&cc, g_cc);
    cudaGetSymbolAddress((void**)&os, g_os);
    cudaGetSymbolAddress((void**)&h, g_h);
    cudaGetSymbolAddress((void**)&w, g_w);

    const size_t M1 = 1024ull * 1024;
    __half *wqkv = w;                    // rows 0..3071 (Wq|Wk|Wv)
    __half *wo   = w + 3*M1;
    __half *f1w1 = w + 4*M1;
    __half *f2w1 = w + 6*M1;
    __half *f1w2 = w + 8*M1;
    __half *f2w2 = w + 10*M1;
    __half *h0 = h, *h1 = h + 8192ull * 2048;

    cudaFuncSetAttribute(gemm_mma<0>, cudaFuncAttributeMaxDynamicSharedMemorySize, GEMM_SMEM);
    cudaFuncSetAttribute(gemm_mma<1>, cudaFuncAttributeMaxDynamicSharedMemorySize, GEMM_SMEM);
    cudaFuncSetAttribute(gemm_mma<2>, cudaFuncAttributeMaxDynamicSharedMemorySize, GEMM_SMEM);
    cudaFuncSetAttribute(gemm_mma<3>, cudaFuncAttributeMaxDynamicSharedMemorySize, GEMM_SMEM);

    // Fused prep: weight converts + LN1 in one launch
    WPtrs wp;
    wp.w[0] = (const float*)d_in[1];   // Wq
    wp.w[1] = (const float*)d_in[2];   // Wk
    wp.w[2] = (const float*)d_in[3];   // Wv
    wp.w[3] = (const float*)d_in[4];   // Wo
    wp.w[4] = (const float*)d_in[9];   // f1w1
    wp.w[5] = (const float*)d_in[13];  // f2w1
    wp.w[6] = (const float*)d_in[11];  // f1w2
    wp.w[7] = (const float*)d_in[15];  // f2w2
    prep_kernel<<<20480, 256>>>(wp, w, input, ln1w, ln1b, xs);

    // QKV merged projection (M=16384, N=3072, K=1024) -> qkv (fp16)
    {
        GPair P{};
        P.A[0] = P.A[1] = xs;
        P.B[0] = P.B[1] = wqkv;
        P.Ch[0] = P.Ch[1] = qkv;
        gemm_mma<0><<<dim3(24, 128, 1), 256, GEMM_SMEM>>>(P, 1024, 1024, 0, 3072, 1024);
    }

    // attention -> concat (fp16)
    attn_kernel<<<8192, 128>>>(qkv, cc);

    // O projection + residual -> out1 (fp32)
    {
        GPair P{};
        P.A[0] = P.A[1] = cc;
        P.B[0] = P.B[1] = wo;
        P.res[0] = P.res[1] = input;
        P.C[0] = P.C[1] = out1;
        gemm_mma<1><<<dim3(8, 128, 1), 256, GEMM_SMEM>>>(P, 1024, 1024, 1024, 1024, 1024);
    }

    // LN2 -> os (fp16)
    ln_kernel<<<8192, 256>>>(out1, ln2w, ln2b, os);

    // FFN layer 1, both slots in one launch (M=8192, N=2048, K=1024) -> h fp16
    {
        GPair P{};
        P.A[0] = os;   P.A[1] = os + 1024;
        P.B[0] = f1w1; P.B[1] = f2w1;
        P.bias[0] = f1b1; P.bias[1] = f2b1;
        P.Ch[0] = h0; P.Ch[1] = h1;
        gemm_mma<2><<<dim3(16, 64, 2), 256, GEMM_SMEM>>>(P, 2048, 1024, 0, 2048, 1024);
    }

    // FFN layer 2 + residual, both slots in one launch (M=8192, N=1024, K=2048)
    {
        GPair P{};
        P.A[0] = h0;   P.A[1] = h1;
        P.B[0] = f1w2; P.B[1] = f2w2;
        P.bias[0] = f1b2; P.bias[1] = f2b2;
        P.res[0] = out1;  P.res[1] = out1 + 1024;
        P.C[0] = out;     P.C[1] = out + 1024;
        gemm_mma<3><<<dim3(8, 64, 2), 256, GEMM_SMEM>>>(P, 2048, 2048, 2048, 2048, 2048);
    }
}

// round 15
// speedup vs baseline: 1.0188x; 1.0034x over previous
#include <cuda_runtime.h>
#include <cuda_fp16.h>
#include <math.h>
#include <stdint.h>

// ===========================================================================
// B=8192, S=2, E=1024 -> 16384 token rows. All GEMMs NT vs (out,in) weights.
// GEMM: plain fp16 mma.sync m16n8k16, fp32 accumulate (R11 config verbatim:
// 128x128 tile, K-chunk 128, 3-stage 64KB cp.async, 8 warps 2Mx4N).
// R15: prep weight-convert at MLP=4 (16 floats/thread), attention at 256
// threads. GEMMs and structure otherwise identical to R14 (best: 1124.7us).
// ===========================================================================

#define NTOK 16384ull

__device__ __align__(256) __half g_qkv[NTOK * 3072];
__device__ __align__(256) float g_out1[NTOK * 1024];
__device__ __align__(256) __half g_xs[NTOK * 1024];
__device__ __align__(256) __half g_cc[NTOK * 1024];
__device__ __align__(256) __half g_os[NTOK * 1024];
__device__ __align__(256) __half g_h[2ull * 8192 * 2048];
__device__ __align__(256) __half g_w[12ull * 1024 * 1024];

// ---------------- helpers ---------------------------------------------------
__device__ __forceinline__ uint32_t smem_u32(const void* p) {
    return (uint32_t)__cvta_generic_to_shared(p);
}
__device__ __forceinline__ void cp16(uint32_t dst, const void* src) {
    asm volatile("cp.async.cg.shared.global [%0], [%1], 16;\n" :: "r"(dst), "l"(src));
}
__device__ __forceinline__ void cp_commit() {
    asm volatile("cp.async.commit_group;\n" ::: "memory");
}
__device__ __forceinline__ void cp_wait1() {
    asm volatile("cp.async.wait_group 1;\n" ::: "memory");
}
__device__ __forceinline__ void ldsm4(uint32_t (&r)[4], uint32_t addr) {
    asm volatile("ldmatrix.sync.aligned.m8n8.x4.shared.b16 {%0,%1,%2,%3}, [%4];"
                 : "=r"(r[0]), "=r"(r[1]), "=r"(r[2]), "=r"(r[3]) : "r"(addr));
}
__device__ __forceinline__ void mma_f16(float (&d)[4], const uint32_t (&a)[4],
                                        uint32_t b0, uint32_t b1) {
    asm volatile(
        "mma.sync.aligned.m16n8k16.row.col.f32.f16.f16.f32 "
        "{%0,%1,%2,%3}, {%4,%5,%6,%7}, {%8,%9}, {%0,%1,%2,%3};"
        : "+f"(d[0]), "+f"(d[1]), "+f"(d[2]), "+f"(d[3])
        : "r"(a[0]), "r"(a[1]), "r"(a[2]), "r"(a[3]), "r"(b0), "r"(b1));
}

// ---------------------------------------------------------------------------
// Fused prep:
//   blocks [0,3072):       weight fp32->fp16, 16 floats per thread (MLP=4)
//     segs 0-3 (1M floats): 256 blocks each;  segs 4-7 (2M): 512 blocks each
//   blocks [3072,11264):   joint LayerNorm-1 (2048 elems/batch) -> fp16
// ---------------------------------------------------------------------------
struct WPtrs { const float* w[8]; };

#define PREP_WBLK 3072
#define PREP_GRID (PREP_WBLK + 8192)

__global__ void __launch_bounds__(256) prep_kernel(
    WPtrs wp, __half* __restrict__ wout,
    const float* __restrict__ x, const float* __restrict__ lw,
    const float* __restrict__ lb, __half* __restrict__ y)
{
    int bid = blockIdx.x;
    int tid = threadIdx.x;
    if (bid < PREP_WBLK) {
        const size_t M1 = 1024ull * 1024;
        int seg, lbk;
        if (bid < 1024) {
            seg = bid >> 8;
            lbk = bid & 255;
        } else {
            seg = 4 + ((bid - 1024) >> 9);
            lbk = (bid - 1024) & 511;
        }
        size_t dstoff = (seg < 4) ? (size_t)seg * M1
                                  : (size_t)(4 + 2 * (seg - 4)) * M1;
        const float* src = wp.w[seg];
        size_t i = (size_t)lbk * 4096 + (size_t)tid * 16;
        // 4 independent float4 loads (MLP=4)
        float4 v0 = *(const float4*)(src + i);
        float4 v1 = *(const float4*)(src + i + 4);
        float4 v2 = *(const float4*)(src + i + 8);
        float4 v3 = *(const float4*)(src + i + 12);
        __half* d = wout + dstoff + i;
        *(__half2*)(d + 0)  = __floats2half2_rn(v0.x, v0.y);
        *(__half2*)(d + 2)  = __floats2half2_rn(v0.z, v0.w);
        *(__half2*)(d + 4)  = __floats2half2_rn(v1.x, v1.y);
        *(__half2*)(d + 6)  = __floats2half2_rn(v1.z, v1.w);
        *(__half2*)(d + 8)  = __floats2half2_rn(v2.x, v2.y);
        *(__half2*)(d + 10) = __floats2half2_rn(v2.z, v2.w);
        *(__half2*)(d + 12) = __floats2half2_rn(v3.x, v3.y);
        *(__half2*)(d + 14) = __floats2half2_rn(v3.z, v3.w);
        return;
    }

    // ---- LayerNorm path ----
    int batch = bid - PREP_WBLK;
    const float4* xv = (const float4*)(x + (size_t)batch * 2048);
    float4 v0 = xv[tid];
    float4 v1 = xv[tid + 256];
    float s  = v0.x + v0.y + v0.z + v0.w + v1.x + v1.y + v1.z + v1.w;
    float ss = v0.x*v0.x + v0.y*v0.y + v0.z*v0.z + v0.w*v0.w
             + v1.x*v1.x + v1.y*v1.y + v1.z*v1.z + v1.w*v1.w;
#pragma unroll
    for (int o = 16; o > 0; o >>= 1) {
        s  += __shfl_xor_sync(0xffffffffu, s,  o);
        ss += __shfl_xor_sync(0xffffffffu, ss, o);
    }
    __shared__ float rs[8], rss[8];
    __shared__ float s_mean, s_rstd;
    if ((tid & 31) == 0) { rs[tid >> 5] = s; rss[tid >> 5] = ss; }
    __syncthreads();
    if (tid == 0) {
        float ts = 0.f, tss = 0.f;
#pragma unroll
        for (int i = 0; i < 8; i++) { ts += rs[i]; tss += rss[i]; }
        float m   = ts * (1.f / 2048.f);
        float var = tss * (1.f / 2048.f) - m * m;
        s_mean = m;
        s_rstd = rsqrtf(var + 1e-5f);
    }
    __syncthreads();
    float m = s_mean, r = s_rstd;
    const float4* wv = (const float4*)lw;
    const float4* bv = (const float4*)lb;
    float4 w0 = wv[tid], w1 = wv[tid + 256];
    float4 b0 = bv[tid], b1 = bv[tid + 256];
    size_t base = (size_t)batch * 2048 + tid * 4;
    *(__half2*)(y + base) = __floats2half2_rn(
        (v0.x - m) * r * w0.x + b0.x, (v0.y - m) * r * w0.y + b0.y);
    *(__half2*)(y + base + 2) = __floats2half2_rn(
        (v0.z - m) * r * w0.z + b0.z, (v0.w - m) * r * w0.w + b0.w);
    *(__half2*)(y + base + 1024) = __floats2half2_rn(
        (v1.x - m) * r * w1.x + b1.x, (v1.y - m) * r * w1.y + b1.y);
    *(__half2*)(y + base + 1026) = __floats2half2_rn(
        (v1.z - m) * r * w1.z + b1.z, (v1.w - m) * r * w1.w + b1.w);
}

// ---------------------------------------------------------------------------
// Standalone joint LayerNorm (for LN2, fp32 in -> fp16 out)
// ---------------------------------------------------------------------------
__global__ void __launch_bounds__(256) ln_kernel(const float* __restrict__ x,
                                                 const float* __restrict__ w,
                                                 const float* __restrict__ bb,
                                                 __half* __restrict__ y) {
    int batch = blockIdx.x;
    int tid = threadIdx.x;
    const float4* xv = (const float4*)(x + (size_t)batch * 2048);
    float4 v0 = xv[tid];
    float4 v1 = xv[tid + 256];
    float s  = v0.x + v0.y + v0.z + v0.w + v1.x + v1.y + v1.z + v1.w;
    float ss = v0.x*v0.x + v0.y*v0.y + v0.z*v0.z + v0.w*v0.w
             + v1.x*v1.x + v1.y*v1.y + v1.z*v1.z + v1.w*v1.w;
#pragma unroll
    for (int o = 16; o > 0; o >>= 1) {
        s  += __shfl_xor_sync(0xffffffffu, s,  o);
        ss += __shfl_xor_sync(0xffffffffu, ss, o);
    }
    __shared__ float rs[8], rss[8];
    __shared__ float s_mean, s_rstd;
    if ((tid & 31) == 0) { rs[tid >> 5] = s; rss[tid >> 5] = ss; }
    __syncthreads();
    if (tid == 0) {
        float ts = 0.f, tss = 0.f;
#pragma unroll
        for (int i = 0; i < 8; i++) { ts += rs[i]; tss += rss[i]; }
        float m   = ts * (1.f / 2048.f);
        float var = tss * (1.f / 2048.f) - m * m;
        s_mean = m;
        s_rstd = rsqrtf(var + 1e-5f);
    }
    __syncthreads();
    float m = s_mean, r = s_rstd;
    const float4* wv = (const float4*)w;
    const float4* bv = (const float4*)bb;
    float4 w0 = wv[tid], w1 = wv[tid + 256];
    float4 b0 = bv[tid], b1 = bv[tid + 256];
    size_t base = (size_t)batch * 2048 + tid * 4;
    *(__half2*)(y + base) = __floats2half2_rn(
        (v0.x - m) * r * w0.x + b0.x, (v0.y - m) * r * w0.y + b0.y);
    *(__half2*)(y + base + 2) = __floats2half2_rn(
        (v0.z - m) * r * w0.z + b0.z, (v0.w - m) * r * w0.w + b0.w);
    *(__half2*)(y + base + 1024) = __floats2half2_rn(
        (v1.x - m) * r * w1.x + b1.x, (v1.y - m) * r * w1.y + b1.y);
    *(__half2*)(y + base + 1026) = __floats2half2_rn(
        (v1.z - m) * r * w1.z + b1.z, (v1.w - m) * r * w1.w + b1.w);
}

// ---------------------------------------------------------------------------
// Attention per batch (S=2; head h = col % 16), fp16 qkv -> concat fp16.
// 256 threads (was 128): halves per-thread serial load chain.
// qkv layout: row (b*2+s) of 3072 halves = [q(1024) | k(1024) | v(1024)]
// ---------------------------------------------------------------------------
__global__ void __launch_bounds__(256) attn_kernel(const __half* __restrict__ qkv,
                                                   __half* __restrict__ oc) {
    int b = blockIdx.x;
    int tid = threadIdx.x;
    __shared__ float sq[2048], sk[2048], sv[2048];
    __shared__ float ssc[16][2][2];
    __shared__ float sp[16][2][2];

#pragma unroll
    for (int s = 0; s < 2; s++) {
        const __half2* row = (const __half2*)(qkv + ((size_t)b * 2 + s) * 3072);
#pragma unroll
        for (int i = tid; i < 512; i += 256) {
            ((float2*)sq)[s * 512 + i] = __half22float2(row[i]);
            ((float2*)sk)[s * 512 + i] = __half22float2(row[512 + i]);
            ((float2*)sv)[s * 512 + i] = __half22float2(row[1024 + i]);
        }
    }
    __syncthreads();

    if (tid < 64) {
        int h = tid >> 2, s = (tid >> 1) & 1, t = tid & 1;
        float acc = 0.f;
#pragma unroll 8
        for (int d = 0; d < 64; d++)
            acc += sq[s * 1024 + d * 16 + h] * sk[t * 1024 + d * 16 + h];
        ssc[h][s][t] = acc * 0.125f;
    }
    __syncthreads();

    if (tid < 32) {
        int h = tid >> 1, s = tid & 1;
        float a0 = ssc[h][s][0], a1 = ssc[h][s][1];
        float mx = fmaxf(a0, a1);
        float e0 = expf(a0 - mx), e1 = expf(a1 - mx);
        float inv = 1.f / (e0 + e1);
        sp[h][s][0] = e0 * inv;
        sp[h][s][1] = e1 * inv;
    }
    __syncthreads();

    size_t ob = (size_t)b * 2048;
#pragma unroll
    for (int i = tid * 2; i < 2048; i += 512) {
        int s = i >> 10;
        int c0 = i & 1023;
        int h0 = c0 & 15, h1 = (c0 + 1) & 15;
        float va = sp[h0][s][0] * sv[c0] + sp[h0][s][1] * sv[1024 + c0];
        float vb = sp[h1][s][0] * sv[c0 + 1] + sp[h1][s][1] * sv[1024 + c0 + 1];
        *(__half2*)(oc + ob + i) = __floats2half2_rn(va, vb);
    }
}

// ---------------------------------------------------------------------------
// Plain fp16 mma.sync GEMM (R11 config, unchanged):  C = epi( A @ B^T ).
// Tile 128x128, K-chunk 128, 8 warps (2M x 4N), 3-stage cp.async (64KB
// stages, 192KB), one barrier per chunk, early issue for c+2.
// smem rows 256B (128 fp16); swizzle: c16 ^ (row & 7).
// gridDim.z indexes pointer sets (merged launches).
// EPI: 0 plain -> fp16; 1 +res -> fp32; 2 tanh(+bias)->fp16; 3 tanh(+bias)+res
// ---------------------------------------------------------------------------
#define A_OFF 0
#define B_OFF 32768
#define STAGE_BYTES 65536
#define NSTAGE 3
#define GEMM_SMEM (NSTAGE * STAGE_BYTES)

struct GPair {
    const __half *A[2], *B[2];
    const float *bias[2], *res[2];
    float *C[2];
    __half *Ch[2];
};

template <int EPI>
__global__ void __launch_bounds__(256) gemm_mma(
    GPair P, int lda, int ldb, int ldres, int ldc, int K)
{
    extern __shared__ __align__(128) char smem[];
    const uint32_t sb = smem_u32(smem);
    const int z = blockIdx.z;
    const int tid = threadIdx.x;
    const int wid = tid >> 5, lane = tid & 31;
    const int bm = blockIdx.y * 128, bn = blockIdx.x * 128;
    const int wm = wid & 1, wn = wid >> 1;
    const int nch = K >> 7;

    float acc[4][4][4];
#pragma unroll
    for (int i = 0; i < 4; i++)
#pragma unroll
        for (int j = 0; j < 4; j++)
#pragma unroll
            for (int r = 0; r < 4; r++) acc[i][j][r] = 0.f;

    // ---- load geometry: 8 passes x 2 matrices, 16B each thread ------------
    const int lrow = tid >> 4, lc16 = tid & 15;
    const uint32_t a_s0 = (uint32_t)(lrow * 256 + ((lc16 ^ (lrow & 7)) << 4));
    const uint32_t a_g0 = (uint32_t)(((bm + lrow) * lda + lc16 * 8) * 2);
    const uint32_t b_g0 = (uint32_t)(((bn + lrow) * ldb + lc16 * 8) * 2);
    const uint32_t a_gstep = (uint32_t)(lda << 5);   // 16 rows * lda * 2B
    const uint32_t b_gstep = (uint32_t)(ldb << 5);
    const char* Ap = (const char*)P.A[z];
    const char* Bp = (const char*)P.B[z];

    auto load_stage = [&](int stage, int c) {
        if (c < nch) {
            const uint32_t s0 = sb + stage * STAGE_BYTES;
            const uint32_t kadd = (uint32_t)c << 8;   // c*256 bytes
#pragma unroll
            for (int j = 0; j < 8; j++) {
                cp16(s0 + A_OFF + a_s0 + j * 4096, Ap + a_g0 + j * a_gstep + kadd);
                cp16(s0 + B_OFF + a_s0 + j * 4096, Bp + b_g0 + j * b_gstep + kadd);
            }
        }
        cp_commit();
    };

    // ---- ldmatrix per-lane geometry ---------------------------------------
    const int r16 = (lane & 7) + (((lane >> 3) & 1) << 3);
    const int cko = lane >> 4;
    uint32_t arow[4]; int axr[4];
#pragma unroll
    for (int tm = 0; tm < 4; tm++) {
        int row = wm * 64 + tm * 16 + r16;
        arow[tm] = row * 256;
        axr[tm] = row & 7;
    }
    uint32_t brow[2]; int bxr[2];
#pragma unroll
    for (int g = 0; g < 2; g++) {
        int row = wn * 32 + g * 16 + r16;
        brow[g] = row * 256;
        bxr[g] = row & 7;
    }

    load_stage(0, 0);
    load_stage(1, 1);

    int stage = 0;
    for (int c = 0; c < nch; c++) {
        cp_wait1();           // chunk c resident
        __syncthreads();      // all warps done with chunk c-1's stage
        int nstage = stage + 2;
        if (nstage >= NSTAGE) nstage -= NSTAGE;
        load_stage(nstage, c + 2);   // overwrites c-1's stage (safe)

        const uint32_t s0 = sb + stage * STAGE_BYTES;
#pragma unroll
        for (int kk = 0; kk < 8; kk++) {
            const int j16 = (kk << 1) | cko;
            uint32_t ar[4][4], br[2][4];
#pragma unroll
            for (int tm = 0; tm < 4; tm++) {
                uint32_t off = arow[tm] + ((j16 ^ axr[tm]) << 4);
                ldsm4(ar[tm], s0 + A_OFF + off);
            }
#pragma unroll
            for (int g = 0; g < 2; g++) {
                uint32_t off = brow[g] + ((j16 ^ bxr[g]) << 4);
                ldsm4(br[g], s0 + B_OFF + off);
            }
#pragma unroll
            for (int tm = 0; tm < 4; tm++)
#pragma unroll
                for (int tn = 0; tn < 4; tn++) {
                    const int g = tn >> 1, h = tn & 1;
                    mma_f16(acc[tm][tn], ar[tm], br[g][h], br[g][h + 2]);
                }
        }
        if (++stage >= NSTAGE) stage -= NSTAGE;
    }

    // Epilogue
    const float* bias = P.bias[z];
    const float* res  = P.res[z];
    float* C = P.C[z];
    __half* Ch = P.Ch[z];
#pragma unroll
    for (int tm = 0; tm < 4; tm++) {
#pragma unroll
        for (int tn = 0; tn < 4; tn++) {
            const int row0 = bm + wm * 64 + tm * 16 + (lane >> 2);
            const int col  = bn + wn * 32 + tn * 8 + (lane & 3) * 2;
#pragma unroll
            for (int hrow = 0; hrow < 2; hrow++) {
                const int row = row0 + hrow * 8;
                float d0 = acc[tm][tn][hrow * 2];
                float d1 = acc[tm][tn][hrow * 2 + 1];
                if (EPI == 0) {
                    *(__half2*)(Ch + (size_t)row * ldc + col) =
                        __floats2half2_rn(d0, d1);
                } else if (EPI == 1) {
                    float2 rv = *(const float2*)(res + (size_t)row * ldres + col);
                    *(float2*)(C + (size_t)row * ldc + col) =
                        make_float2(d0 + rv.x, d1 + rv.y);
                } else if (EPI == 2) {
                    float2 bv = *(const float2*)(bias + col);
                    *(__half2*)(Ch + (size_t)row * ldc + col) =
                        __floats2half2_rn(tanhf(d0 + bv.x), tanhf(d1 + bv.y));
                } else {
                    float2 bv = *(const float2*)(bias + col);
                    float2 rv = *(const float2*)(res + (size_t)row * ldres + col);
                    *(float2*)(C + (size_t)row * ldc + col) =
                        make_float2(tanhf(d0 + bv.x) + rv.x, tanhf(d1 + bv.y) + rv.y);
                }
            }
        }
    }
}

// ---------------------------------------------------------------------------
// Orchestration
// ---------------------------------------------------------------------------
extern "C" void kernel_launch(void* const* d_in, const int* in_sizes, int n_in,
                              void* d_out, int out_size) {
    (void)in_sizes; (void)n_in; (void)out_size;
    const float* input = (const float*)d_in[0];
    const float* ln1w = (const float*)d_in[5];
    const float* ln1b = (const float*)d_in[6];
    const float* ln2w = (const float*)d_in[7];
    const float* ln2b = (const float*)d_in[8];
    const float* f1b1 = (const float*)d_in[10];
    const float* f1b2 = (const float*)d_in[12];
    const float* f2b1 = (const float*)d_in[14];
    const float* f2b2 = (const float*)d_in[16];
    float* out = (float*)d_out;

    float* out1;
    __half *qkv, *xs, *cc, *os, *h, *w;
    cudaGetSymbolAddress((void**)&qkv, g_qkv);
    cudaGetSymbolAddress((void**)&out1, g_out1);
    cudaGetSymbolAddress((void**)&xs, g_xs);
    cudaGetSymbolAddress((void**)&cc, g_cc);
    cudaGetSymbolAddress((void**)&os, g_os);
    cudaGetSymbolAddress((void**)&h, g_h);
    cudaGetSymbolAddress((void**)&w, g_w);

    const size_t M1 = 1024ull * 1024;
    __half *wqkv = w;                    // rows 0..3071 (Wq|Wk|Wv)
    __half *wo   = w + 3*M1;
    __half *f1w1 = w + 4*M1;
    __half *f2w1 = w + 6*M1;
    __half *f1w2 = w + 8*M1;
    __half *f2w2 = w + 10*M1;
    __half *h0 = h, *h1 = h + 8192ull * 2048;

    cudaFuncSetAttribute(gemm_mma<0>, cudaFuncAttributeMaxDynamicSharedMemorySize, GEMM_SMEM);
    cudaFuncSetAttribute(gemm_mma<1>, cudaFuncAttributeMaxDynamicSharedMemorySize, GEMM_SMEM);
    cudaFuncSetAttribute(gemm_mma<2>, cudaFuncAttributeMaxDynamicSharedMemorySize, GEMM_SMEM);
    cudaFuncSetAttribute(gemm_mma<3>, cudaFuncAttributeMaxDynamicSharedMemorySize, GEMM_SMEM);

    // Fused prep: weight converts (MLP=4) + LN1 in one launch
    WPtrs wp;
    wp.w[0] = (const float*)d_in[1];   // Wq
    wp.w[1] = (const float*)d_in[2];   // Wk
    wp.w[2] = (const float*)d_in[3];   // Wv
    wp.w[3] = (const float*)d_in[4];   // Wo
    wp.w[4] = (const float*)d_in[9];   // f1w1
    wp.w[5] = (const float*)d_in[13];  // f2w1
    wp.w[6] = (const float*)d_in[11];  // f1w2
    wp.w[7] = (const float*)d_in[15];  // f2w2
    prep_kernel<<<PREP_GRID, 256>>>(wp, w, input, ln1w, ln1b, xs);

    // QKV merged projection (M=16384, N=3072, K=1024) -> qkv (fp16)
    {
        GPair P{};
        P.A[0] = P.A[1] = xs;
        P.B[0] = P.B[1] = wqkv;
        P.Ch[0] = P.Ch[1] = qkv;
        gemm_mma<0><<<dim3(24, 128, 1), 256, GEMM_SMEM>>>(P, 1024, 1024, 0, 3072, 1024);
    }

    // attention -> concat (fp16)
    attn_kernel<<<8192, 256>>>(qkv, cc);

    // O projection + residual -> out1 (fp32)
    {
        GPair P{};
        P.A[0] = P.A[1] = cc;
        P.B[0] = P.B[1] = wo;
        P.res[0] = P.res[1] = input;
        P.C[0] = P.C[1] = out1;
        gemm_mma<1><<<dim3(8, 128, 1), 256, GEMM_SMEM>>>(P, 1024, 1024, 1024, 1024, 1024);
    }

    // LN2 -> os (fp16)
    ln_kernel<<<8192, 256>>>(out1, ln2w, ln2b, os);

    // FFN layer 1, both slots in one launch (M=8192, N=2048, K=1024) -> h fp16
    {
        GPair P{};
        P.A[0] = os;   P.A[1] = os + 1024;
        P.B[0] = f1w1; P.B[1] = f2w1;
        P.bias[0] = f1b1; P.bias[1] = f2b1;
        P.Ch[0] = h0; P.Ch[1] = h1;
        gemm_mma<2><<<dim3(16, 64, 2), 256, GEMM_SMEM>>>(P, 2048, 1024, 0, 2048, 1024);
    }

    // FFN layer 2 + residual, both slots in one launch (M=8192, N=1024, K=2048)
    {
        GPair P{};
        P.A[0] = h0;   P.A[1] = h1;
        P.B[0] = f1w2; P.B[1] = f2w2;
        P.bias[0] = f1b2; P.bias[1] = f2b2;
        P.res[0] = out1;  P.res[1] = out1 + 1024;
        P.C[0] = out;     P.C[1] = out + 1024;
        gemm_mma<3><<<dim3(8, 64, 2), 256, GEMM_SMEM>>>(P, 2048, 2048, 2048, 2048, 2048);
    }
}

// round 16
// speedup vs baseline: 1.0847x; 1.0647x over previous
#include <cuda_runtime.h>
#include <cuda_fp16.h>
#include <math.h>
#include <stdint.h>

// ===========================================================================
// B=8192, S=2, E=1024 -> 16384 token rows. All GEMMs NT vs (out,in) weights.
// GEMM: plain fp16 mma.sync m16n8k16, fp32 accumulate.
// R16: CTA 256x128, 512 threads (16 warps, 4Mx4N, warp tile 64x32 = R11
// per-warp geometry), K-chunk 128 (proven 128-HMMA/warp/barrier cadence),
// 2-stage cp.async (96KB stages, 192KB). prep/attn/ln2 from R15.
// ===========================================================================

#define NTOK 16384ull

__device__ __align__(256) __half g_qkv[NTOK * 3072];
__device__ __align__(256) float g_out1[NTOK * 1024];
__device__ __align__(256) __half g_xs[NTOK * 1024];
__device__ __align__(256) __half g_cc[NTOK * 1024];
__device__ __align__(256) __half g_os[NTOK * 1024];
__device__ __align__(256) __half g_h[2ull * 8192 * 2048];
__device__ __align__(256) __half g_w[12ull * 1024 * 1024];

// ---------------- helpers ---------------------------------------------------
__device__ __forceinline__ uint32_t smem_u32(const void* p) {
    return (uint32_t)__cvta_generic_to_shared(p);
}
__device__ __forceinline__ void cp16(uint32_t dst, const void* src) {
    asm volatile("cp.async.cg.shared.global [%0], [%1], 16;\n" :: "r"(dst), "l"(src));
}
__device__ __forceinline__ void cp_commit() {
    asm volatile("cp.async.commit_group;\n" ::: "memory");
}
__device__ __forceinline__ void cp_wait1() {
    asm volatile("cp.async.wait_group 1;\n" ::: "memory");
}
__device__ __forceinline__ void ldsm4(uint32_t (&r)[4], uint32_t addr) {
    asm volatile("ldmatrix.sync.aligned.m8n8.x4.shared.b16 {%0,%1,%2,%3}, [%4];"
                 : "=r"(r[0]), "=r"(r[1]), "=r"(r[2]), "=r"(r[3]) : "r"(addr));
}
__device__ __forceinline__ void mma_f16(float (&d)[4], const uint32_t (&a)[4],
                                        uint32_t b0, uint32_t b1) {
    asm volatile(
        "mma.sync.aligned.m16n8k16.row.col.f32.f16.f16.f32 "
        "{%0,%1,%2,%3}, {%4,%5,%6,%7}, {%8,%9}, {%0,%1,%2,%3};"
        : "+f"(d[0]), "+f"(d[1]), "+f"(d[2]), "+f"(d[3])
        : "r"(a[0]), "r"(a[1]), "r"(a[2]), "r"(a[3]), "r"(b0), "r"(b1));
}

// ---------------------------------------------------------------------------
// Fused prep (R15): weight fp32->fp16 at MLP=4 + LayerNorm-1.
// ---------------------------------------------------------------------------
struct WPtrs { const float* w[8]; };

#define PREP_WBLK 3072
#define PREP_GRID (PREP_WBLK + 8192)

__global__ void __launch_bounds__(256) prep_kernel(
    WPtrs wp, __half* __restrict__ wout,
    const float* __restrict__ x, const float* __restrict__ lw,
    const float* __restrict__ lb, __half* __restrict__ y)
{
    int bid = blockIdx.x;
    int tid = threadIdx.x;
    if (bid < PREP_WBLK) {
        const size_t M1 = 1024ull * 1024;
        int seg, lbk;
        if (bid < 1024) {
            seg = bid >> 8;
            lbk = bid & 255;
        } else {
            seg = 4 + ((bid - 1024) >> 9);
            lbk = (bid - 1024) & 511;
        }
        size_t dstoff = (seg < 4) ? (size_t)seg * M1
                                  : (size_t)(4 + 2 * (seg - 4)) * M1;
        const float* src = wp.w[seg];
        size_t i = (size_t)lbk * 4096 + (size_t)tid * 16;
        float4 v0 = *(const float4*)(src + i);
        float4 v1 = *(const float4*)(src + i + 4);
        float4 v2 = *(const float4*)(src + i + 8);
        float4 v3 = *(const float4*)(src + i + 12);
        __half* d = wout + dstoff + i;
        *(__half2*)(d + 0)  = __floats2half2_rn(v0.x, v0.y);
        *(__half2*)(d + 2)  = __floats2half2_rn(v0.z, v0.w);
        *(__half2*)(d + 4)  = __floats2half2_rn(v1.x, v1.y);
        *(__half2*)(d + 6)  = __floats2half2_rn(v1.z, v1.w);
        *(__half2*)(d + 8)  = __floats2half2_rn(v2.x, v2.y);
        *(__half2*)(d + 10) = __floats2half2_rn(v2.z, v2.w);
        *(__half2*)(d + 12) = __floats2half2_rn(v3.x, v3.y);
        *(__half2*)(d + 14) = __floats2half2_rn(v3.z, v3.w);
        return;
    }

    int batch = bid - PREP_WBLK;
    const float4* xv = (const float4*)(x + (size_t)batch * 2048);
    float4 v0 = xv[tid];
    float4 v1 = xv[tid + 256];
    float s  = v0.x + v0.y + v0.z + v0.w + v1.x + v1.y + v1.z + v1.w;
    float ss = v0.x*v0.x + v0.y*v0.y + v0.z*v0.z + v0.w*v0.w
             + v1.x*v1.x + v1.y*v1.y + v1.z*v1.z + v1.w*v1.w;
#pragma unroll
    for (int o = 16; o > 0; o >>= 1) {
        s  += __shfl_xor_sync(0xffffffffu, s,  o);
        ss += __shfl_xor_sync(0xffffffffu, ss, o);
    }
    __shared__ float rs[8], rss[8];
    __shared__ float s_mean, s_rstd;
    if ((tid & 31) == 0) { rs[tid >> 5] = s; rss[tid >> 5] = ss; }
    __syncthreads();
    if (tid == 0) {
        float ts = 0.f, tss = 0.f;
#pragma unroll
        for (int i = 0; i < 8; i++) { ts += rs[i]; tss += rss[i]; }
        float m   = ts * (1.f / 2048.f);
        float var = tss * (1.f / 2048.f) - m * m;
        s_mean = m;
        s_rstd = rsqrtf(var + 1e-5f);
    }
    __syncthreads();
    float m = s_mean, r = s_rstd;
    const float4* wv = (const float4*)lw;
    const float4* bv = (const float4*)lb;
    float4 w0 = wv[tid], w1 = wv[tid + 256];
    float4 b0 = bv[tid], b1 = bv[tid + 256];
    size_t base = (size_t)batch * 2048 + tid * 4;
    *(__half2*)(y + base) = __floats2half2_rn(
        (v0.x - m) * r * w0.x + b0.x, (v0.y - m) * r * w0.y + b0.y);
    *(__half2*)(y + base + 2) = __floats2half2_rn(
        (v0.z - m) * r * w0.z + b0.z, (v0.w - m) * r * w0.w + b0.w);
    *(__half2*)(y + base + 1024) = __floats2half2_rn(
        (v1.x - m) * r * w1.x + b1.x, (v1.y - m) * r * w1.y + b1.y);
    *(__half2*)(y + base + 1026) = __floats2half2_rn(
        (v1.z - m) * r * w1.z + b1.z, (v1.w - m) * r * w1.w + b1.w);
}

// ---------------------------------------------------------------------------
// Standalone joint LayerNorm (LN2, fp32 -> fp16)
// ---------------------------------------------------------------------------
__global__ void __launch_bounds__(256) ln_kernel(const float* __restrict__ x,
                                                 const float* __restrict__ w,
                                                 const float* __restrict__ bb,
                                                 __half* __restrict__ y) {
    int batch = blockIdx.x;
    int tid = threadIdx.x;
    const float4* xv = (const float4*)(x + (size_t)batch * 2048);
    float4 v0 = xv[tid];
    float4 v1 = xv[tid + 256];
    float s  = v0.x + v0.y + v0.z + v0.w + v1.x + v1.y + v1.z + v1.w;
    float ss = v0.x*v0.x + v0.y*v0.y + v0.z*v0.z + v0.w*v0.w
             + v1.x*v1.x + v1.y*v1.y + v1.z*v1.z + v1.w*v1.w;
#pragma unroll
    for (int o = 16; o > 0; o >>= 1) {
        s  += __shfl_xor_sync(0xffffffffu, s,  o);
        ss += __shfl_xor_sync(0xffffffffu, ss, o);
    }
    __shared__ float rs[8], rss[8];
    __shared__ float s_mean, s_rstd;
    if ((tid & 31) == 0) { rs[tid >> 5] = s; rss[tid >> 5] = ss; }
    __syncthreads();
    if (tid == 0) {
        float ts = 0.f, tss = 0.f;
#pragma unroll
        for (int i = 0; i < 8; i++) { ts += rs[i]; tss += rss[i]; }
        float m   = ts * (1.f / 2048.f);
        float var = tss * (1.f / 2048.f) - m * m;
        s_mean = m;
        s_rstd = rsqrtf(var + 1e-5f);
    }
    __syncthreads();
    float m = s_mean, r = s_rstd;
    const float4* wv = (const float4*)w;
    const float4* bv = (const float4*)bb;
    float4 w0 = wv[tid], w1 = wv[tid + 256];
    float4 b0 = bv[tid], b1 = bv[tid + 256];
    size_t base = (size_t)batch * 2048 + tid * 4;
    *(__half2*)(y + base) = __floats2half2_rn(
        (v0.x - m) * r * w0.x + b0.x, (v0.y - m) * r * w0.y + b0.y);
    *(__half2*)(y + base + 2) = __floats2half2_rn(
        (v0.z - m) * r * w0.z + b0.z, (v0.w - m) * r * w0.w + b0.w);
    *(__half2*)(y + base + 1024) = __floats2half2_rn(
        (v1.x - m) * r * w1.x + b1.x, (v1.y - m) * r * w1.y + b1.y);
    *(__half2*)(y + base + 1026) = __floats2half2_rn(
        (v1.z - m) * r * w1.z + b1.z, (v1.w - m) * r * w1.w + b1.w);
}

// ---------------------------------------------------------------------------
// Attention per batch (S=2; head h = col % 16), fp16 qkv -> concat fp16.
// ---------------------------------------------------------------------------
__global__ void __launch_bounds__(256) attn_kernel(const __half* __restrict__ qkv,
                                                   __half* __restrict__ oc) {
    int b = blockIdx.x;
    int tid = threadIdx.x;
    __shared__ float sq[2048], sk[2048], sv[2048];
    __shared__ float ssc[16][2][2];
    __shared__ float sp[16][2][2];

#pragma unroll
    for (int s = 0; s < 2; s++) {
        const __half2* row = (const __half2*)(qkv + ((size_t)b * 2 + s) * 3072);
#pragma unroll
        for (int i = tid; i < 512; i += 256) {
            ((float2*)sq)[s * 512 + i] = __half22float2(row[i]);
            ((float2*)sk)[s * 512 + i] = __half22float2(row[512 + i]);
            ((float2*)sv)[s * 512 + i] = __half22float2(row[1024 + i]);
        }
    }
    __syncthreads();

    if (tid < 64) {
        int h = tid >> 2, s = (tid >> 1) & 1, t = tid & 1;
        float acc = 0.f;
#pragma unroll 8
        for (int d = 0; d < 64; d++)
            acc += sq[s * 1024 + d * 16 + h] * sk[t * 1024 + d * 16 + h];
        ssc[h][s][t] = acc * 0.125f;
    }
    __syncthreads();

    if (tid < 32) {
        int h = tid >> 1, s = tid & 1;
        float a0 = ssc[h][s][0], a1 = ssc[h][s][1];
        float mx = fmaxf(a0, a1);
        float e0 = expf(a0 - mx), e1 = expf(a1 - mx);
        float inv = 1.f / (e0 + e1);
        sp[h][s][0] = e0 * inv;
        sp[h][s][1] = e1 * inv;
    }
    __syncthreads();

    size_t ob = (size_t)b * 2048;
#pragma unroll
    for (int i = tid * 2; i < 2048; i += 512) {
        int s = i >> 10;
        int c0 = i & 1023;
        int h0 = c0 & 15, h1 = (c0 + 1) & 15;
        float va = sp[h0][s][0] * sv[c0] + sp[h0][s][1] * sv[1024 + c0];
        float vb = sp[h1][s][0] * sv[c0 + 1] + sp[h1][s][1] * sv[1024 + c0 + 1];
        *(__half2*)(oc + ob + i) = __floats2half2_rn(va, vb);
    }
}

// ---------------------------------------------------------------------------
// Plain fp16 mma.sync GEMM:  C = epi( A @ B^T ).
// CTA 256x128, K-chunk 128, 512 threads (16 warps: 4M x 4N, warp tile 64x32),
// 2-stage cp.async (A 64KB + B 32KB = 96KB stages, 192KB). Two barriers per
// chunk (2-stage). smem rows 256B; swizzle c16 ^ (row & 7).
// gridDim.z indexes pointer sets (merged launches).
// EPI: 0 plain -> fp16; 1 +res -> fp32; 2 tanh(+bias)->fp16; 3 tanh(+bias)+res
// ---------------------------------------------------------------------------
#define A_OFF 0
#define B_OFF 65536
#define STAGE_BYTES 98304
#define GEMM_SMEM (2 * STAGE_BYTES)

struct GPair {
    const __half *A[2], *B[2];
    const float *bias[2], *res[2];
    float *C[2];
    __half *Ch[2];
};

template <int EPI>
__global__ void __launch_bounds__(512) gemm_mma(
    GPair P, int lda, int ldb, int ldres, int ldc, int K)
{
    extern __shared__ __align__(128) char smem[];
    const uint32_t sb = smem_u32(smem);
    const int z = blockIdx.z;
    const int tid = threadIdx.x;
    const int wid = tid >> 5, lane = tid & 31;
    const int bm = blockIdx.y * 256, bn = blockIdx.x * 128;
    const int wm = wid & 3, wn = wid >> 2;   // 4M x 4N, warp tile 64x32
    const int nch = K >> 7;

    float acc[4][4][4];
#pragma unroll
    for (int i = 0; i < 4; i++)
#pragma unroll
        for (int j = 0; j < 4; j++)
#pragma unroll
            for (int r = 0; r < 4; r++) acc[i][j][r] = 0.f;

    // ---- load geometry: lrow = tid>>4 (0..31), lc16 = tid&15 --------------
    // A: 256 rows -> 8 passes of 32; B: 128 rows -> 4 passes. Row step 32
    // preserves swizzle bits (row & 7).
    const int lrow = tid >> 4, lc16 = tid & 15;
    const uint32_t s_off = (uint32_t)(lrow * 256 + ((lc16 ^ (lrow & 7)) << 4));
    const uint32_t a_g0 = (uint32_t)(((bm + lrow) * lda + lc16 * 8) * 2);
    const uint32_t b_g0 = (uint32_t)(((bn + lrow) * ldb + lc16 * 8) * 2);
    const uint32_t a_gstep = (uint32_t)(lda << 6);   // 32 rows * lda * 2B
    const uint32_t b_gstep = (uint32_t)(ldb << 6);
    const char* Ap = (const char*)P.A[z];
    const char* Bp = (const char*)P.B[z];

    auto load_stage = [&](int stage, int c) {
        if (c < nch) {
            const uint32_t s0 = sb + stage * STAGE_BYTES;
            const uint32_t kadd = (uint32_t)c << 8;   // c*256 bytes
#pragma unroll
            for (int j = 0; j < 8; j++)
                cp16(s0 + A_OFF + s_off + j * 8192, Ap + a_g0 + j * a_gstep + kadd);
#pragma unroll
            for (int j = 0; j < 4; j++)
                cp16(s0 + B_OFF + s_off + j * 8192, Bp + b_g0 + j * b_gstep + kadd);
        }
        cp_commit();
    };

    // ---- ldmatrix per-lane geometry ---------------------------------------
    const int r16 = (lane & 7) + (((lane >> 3) & 1) << 3);
    const int cko = lane >> 4;
    uint32_t arow[4]; int axr[4];
#pragma unroll
    for (int tm = 0; tm < 4; tm++) {
        int row = wm * 64 + tm * 16 + r16;
        arow[tm] = row * 256;
        axr[tm] = row & 7;
    }
    uint32_t brow[2]; int bxr[2];
#pragma unroll
    for (int g = 0; g < 2; g++) {
        int row = wn * 32 + g * 16 + r16;
        brow[g] = row * 256;
        bxr[g] = row & 7;
    }

    load_stage(0, 0);
    load_stage(1, 1);

    for (int c = 0; c < nch; c++) {
        cp_wait1();           // chunk c resident (c+1 may still be in flight)
        __syncthreads();

        const uint32_t s0 = sb + (c & 1) * STAGE_BYTES;
#pragma unroll
        for (int kk = 0; kk < 8; kk++) {
            const int j16 = (kk << 1) | cko;
            uint32_t ar[4][4], br[2][4];
#pragma unroll
            for (int tm = 0; tm < 4; tm++) {
                uint32_t off = arow[tm] + ((j16 ^ axr[tm]) << 4);
                ldsm4(ar[tm], s0 + A_OFF + off);
            }
#pragma unroll
            for (int g = 0; g < 2; g++) {
                uint32_t off = brow[g] + ((j16 ^ bxr[g]) << 4);
                ldsm4(br[g], s0 + B_OFF + off);
            }
#pragma unroll
            for (int tm = 0; tm < 4; tm++)
#pragma unroll
                for (int tn = 0; tn < 4; tn++) {
                    const int g = tn >> 1, h = tn & 1;
                    mma_f16(acc[tm][tn], ar[tm], br[g][h], br[g][h + 2]);
                }
        }
        __syncthreads();      // all warps done reading this stage
        load_stage(c & 1, c + 2);
    }

    // Epilogue
    const float* bias = P.bias[z];
    const float* res  = P.res[z];
    float* C = P.C[z];
    __half* Ch = P.Ch[z];
#pragma unroll
    for (int tm = 0; tm < 4; tm++) {
#pragma unroll
        for (int tn = 0; tn < 4; tn++) {
            const int row0 = bm + wm * 64 + tm * 16 + (lane >> 2);
            const int col  = bn + wn * 32 + tn * 8 + (lane & 3) * 2;
#pragma unroll
            for (int hrow = 0; hrow < 2; hrow++) {
                const int row = row0 + hrow * 8;
                float d0 = acc[tm][tn][hrow * 2];
                float d1 = acc[tm][tn][hrow * 2 + 1];
                if (EPI == 0) {
                    *(__half2*)(Ch + (size_t)row * ldc + col) =
                        __floats2half2_rn(d0, d1);
                } else if (EPI == 1) {
                    float2 rv = *(const float2*)(res + (size_t)row * ldres + col);
                    *(float2*)(C + (size_t)row * ldc + col) =
                        make_float2(d0 + rv.x, d1 + rv.y);
                } else if (EPI == 2) {
                    float2 bv = *(const float2*)(bias + col);
                    *(__half2*)(Ch + (size_t)row * ldc + col) =
                        __floats2half2_rn(tanhf(d0 + bv.x), tanhf(d1 + bv.y));
                } else {
                    float2 bv = *(const float2*)(bias + col);
                    float2 rv = *(const float2*)(res + (size_t)row * ldres + col);
                    *(float2*)(C + (size_t)row * ldc + col) =
                        make_float2(tanhf(d0 + bv.x) + rv.x, tanhf(d1 + bv.y) + rv.y);
                }
            }
        }
    }
}

// ---------------------------------------------------------------------------
// Orchestration
// ---------------------------------------------------------------------------
extern "C" void kernel_launch(void* const* d_in, const int* in_sizes, int n_in,
                              void* d_out, int out_size) {
    (void)in_sizes; (void)n_in; (void)out_size;
    const float* input = (const float*)d_in[0];
    const float* ln1w = (const float*)d_in[5];
    const float* ln1b = (const float*)d_in[6];
    const float* ln2w = (const float*)d_in[7];
    const float* ln2b = (const float*)d_in[8];
    const float* f1b1 = (const float*)d_in[10];
    const float* f1b2 = (const float*)d_in[12];
    const float* f2b1 = (const float*)d_in[14];
    const float* f2b2 = (const float*)d_in[16];
    float* out = (float*)d_out;

    float* out1;
    __half *qkv, *xs, *cc, *os, *h, *w;
    cudaGetSymbolAddress((void**)&qkv, g_qkv);
    cudaGetSymbolAddress((void**)&out1, g_out1);
    cudaGetSymbolAddress((void**)&xs, g_xs);
    cudaGetSymbolAddress((void**)&cc, g_cc);
    cudaGetSymbolAddress((void**)&os, g_os);
    cudaGetSymbolAddress((void**)&h, g_h);
    cudaGetSymbolAddress((void**)&w, g_w);

    const size_t M1 = 1024ull * 1024;
    __half *wqkv = w;                    // rows 0..3071 (Wq|Wk|Wv)
    __half *wo   = w + 3*M1;
    __half *f1w1 = w + 4*M1;
    __half *f2w1 = w + 6*M1;
    __half *f1w2 = w + 8*M1;
    __half *f2w2 = w + 10*M1;
    __half *h0 = h, *h1 = h + 8192ull * 2048;

    cudaFuncSetAttribute(gemm_mma<0>, cudaFuncAttributeMaxDynamicSharedMemorySize, GEMM_SMEM);
    cudaFuncSetAttribute(gemm_mma<1>, cudaFuncAttributeMaxDynamicSharedMemorySize, GEMM_SMEM);
    cudaFuncSetAttribute(gemm_mma<2>, cudaFuncAttributeMaxDynamicSharedMemorySize, GEMM_SMEM);
    cudaFuncSetAttribute(gemm_mma<3>, cudaFuncAttributeMaxDynamicSharedMemorySize, GEMM_SMEM);

    // Fused prep: weight converts (MLP=4) + LN1 in one launch
    WPtrs wp;
    wp.w[0] = (const float*)d_in[1];   // Wq
    wp.w[1] = (const float*)d_in[2];   // Wk
    wp.w[2] = (const float*)d_in[3];   // Wv
    wp.w[3] = (const float*)d_in[4];   // Wo
    wp.w[4] = (const float*)d_in[9];   // f1w1
    wp.w[5] = (const float*)d_in[13];  // f2w1
    wp.w[6] = (const float*)d_in[11];  // f1w2
    wp.w[7] = (const float*)d_in[15];  // f2w2
    prep_kernel<<<PREP_GRID, 256>>>(wp, w, input, ln1w, ln1b, xs);

    // QKV merged projection (M=16384, N=3072, K=1024) -> qkv (fp16)
    {
        GPair P{};
        P.A[0] = P.A[1] = xs;
        P.B[0] = P.B[1] = wqkv;
        P.Ch[0] = P.Ch[1] = qkv;
        gemm_mma<0><<<dim3(24, 64, 1), 512, GEMM_SMEM>>>(P, 1024, 1024, 0, 3072, 1024);
    }

    // attention -> concat (fp16)
    attn_kernel<<<8192, 256>>>(qkv, cc);

    // O projection + residual -> out1 (fp32)
    {
        GPair P{};
        P.A[0] = P.A[1] = cc;
        P.B[0] = P.B[1] = wo;
        P.res[0] = P.res[1] = input;
        P.C[0] = P.C[1] = out1;
        gemm_mma<1><<<dim3(8, 64, 1), 512, GEMM_SMEM>>>(P, 1024, 1024, 1024, 1024, 1024);
    }

    // LN2 -> os (fp16)
    ln_kernel<<<8192, 256>>>(out1, ln2w, ln2b, os);

    // FFN layer 1, both slots in one launch (M=8192, N=2048, K=1024) -> h fp16
    {
        GPair P{};
        P.A[0] = os;   P.A[1] = os + 1024;
        P.B[0] = f1w1; P.B[1] = f2w1;
        P.bias[0] = f1b1; P.bias[1] = f2b1;
        P.Ch[0] = h0; P.Ch[1] = h1;
        gemm_mma<2><<<dim3(16, 32, 2), 512, GEMM_SMEM>>>(P, 2048, 1024, 0, 2048, 1024);
    }

    // FFN layer 2 + residual, both slots in one launch (M=8192, N=1024, K=2048)
    {
        GPair P{};
        P.A[0] = h0;   P.A[1] = h1;
        P.B[0] = f1w2; P.B[1] = f2w2;
        P.bias[0] = f1b2; P.bias[1] = f2b2;
        P.res[0] = out1;  P.res[1] = out1 + 1024;
        P.C[0] = out;     P.C[1] = out + 1024;
        gemm_mma<3><<<dim3(8, 32, 2), 512, GEMM_SMEM>>>(P, 2048, 2048, 2048, 2048, 2048);
    }
}